// round 14
// baseline (speedup 1.0000x reference)
#include <cuda_runtime.h>
#include <cuda_bf16.h>
#include <math.h>
#include <stdint.h>

// ---------------- problem constants ----------------
#define NN      50000
#define EE      800000
#define ETOT    (EE + NN)
#define F_IN    512
#define NH      8
#define HC      128
#define LBL     40
#define BN_EPS  1e-5f
#define ELU_A   0.2f
#define NSLOPE  0.2f
#define GS      20      // smem row stride in u32 (80B) — conflict-free for LDSM
#define ASZ     (128 * GS)          // u32 per A array
#define BSZ     (64 * GS)           // u32 per B array
#define BUFU    (2 * ASZ + 2 * BSZ) // u32 per buffer (Ah,Al,Bh,Bl) = 7680
#define SMEMB   (2 * BUFU * 4)      // bytes total = 61440

// ---------------- device scratch ----------------
__device__ float g_gbuf[(size_t)NN * HC];
__device__ float g_hbuf[(size_t)NN * HC];
__device__ float g_as[NN * NH];
__device__ float g_ad[NN * NH];
__device__ float g_as2[NN];
__device__ float g_ad2[NN];
__device__ int   g_counts[NN];
__device__ int   g_cursor[NN];
__device__ int   g_offs[NN];
__device__ int   g_esrc[ETOT];
__device__ int   g_total;
__device__ __nv_bfloat16 g_w0h[HC * F_IN];
__device__ __nv_bfloat16 g_w0l[HC * F_IN];
__device__ __nv_bfloat16 g_w1h[HC * HC];
__device__ __nv_bfloat16 g_w1l[HC * HC];
__device__ __nv_bfloat16 g_w2h[LBL * HC];
__device__ __nv_bfloat16 g_w2l[LBL * HC];

// ---------------- CSR build ----------------
__global__ void k_zero() {
    int i = blockIdx.x * blockDim.x + threadIdx.x;
    if (i < NN) { g_counts[i] = 0; g_cursor[i] = 0; }
    if (i == 0) g_total = 0;
}
__global__ void k_count(const int* __restrict__ ei) {
    int i = blockIdx.x * blockDim.x + threadIdx.x;
    if (i >= ETOT) return;
    int d = (i < EE) ? ei[EE + i] : (i - EE);
    atomicAdd(&g_counts[d], 1);
}
__global__ void k_assign() {
    int i = blockIdx.x * blockDim.x + threadIdx.x;
    if (i < NN) g_offs[i] = atomicAdd(&g_total, g_counts[i]);
}
__global__ void k_fill(const int* __restrict__ ei) {
    int i = blockIdx.x * blockDim.x + threadIdx.x;
    if (i >= ETOT) return;
    int s, d;
    if (i < EE) { s = ei[i]; d = ei[EE + i]; }
    else        { s = d = i - EE; }
    int slot = g_offs[d] + atomicAdd(&g_cursor[d], 1);
    g_esrc[slot] = s;
}

// ---------------- weight transpose + bf16 split ----------------
__global__ void k_convW(const float* __restrict__ W, int K, int N,
                        __nv_bfloat16* __restrict__ hi, __nv_bfloat16* __restrict__ lo) {
    int i = blockIdx.x * blockDim.x + threadIdx.x;
    if (i >= K * N) return;
    int k = i / N, n = i - k * N;
    float v = W[i];
    __nv_bfloat16 h = __float2bfloat16(v);
    float r = v - __bfloat162float(h);
    hi[n * K + k] = h;
    lo[n * K + k] = __float2bfloat16(r);
}

// ---------------- asm helpers ----------------
__device__ __forceinline__ void mma16816(float* d,
                                         uint32_t a0, uint32_t a1, uint32_t a2, uint32_t a3,
                                         uint32_t b0, uint32_t b1) {
    asm volatile("mma.sync.aligned.m16n8k16.row.col.f32.bf16.bf16.f32 "
                 "{%0,%1,%2,%3}, {%4,%5,%6,%7}, {%8,%9}, {%0,%1,%2,%3};"
                 : "+f"(d[0]), "+f"(d[1]), "+f"(d[2]), "+f"(d[3])
                 : "r"(a0), "r"(a1), "r"(a2), "r"(a3), "r"(b0), "r"(b1));
}
__device__ __forceinline__ void ldsm4(uint32_t& r0, uint32_t& r1, uint32_t& r2, uint32_t& r3,
                                      uint32_t a) {
    asm volatile("ldmatrix.sync.aligned.m8n8.x4.shared.b16 {%0,%1,%2,%3}, [%4];"
                 : "=r"(r0), "=r"(r1), "=r"(r2), "=r"(r3) : "r"(a));
}

// ---------------- bf16x3 TC GEMM, 128x64 tile, 256 thr, 2 CTA/SM ------------
// Register prefetch (R13) + double-buffered smem: one __syncthreads per tile.
// Schedule: ldg(t+1); compute(cur); stS(nxt); sync.
template<bool FUSE>
__global__ __launch_bounds__(256, 2)
void gemm_tc64(const float* __restrict__ A,
               const __nv_bfloat16* __restrict__ Wh,
               const __nv_bfloat16* __restrict__ Wl,
               float* __restrict__ C, int M, int K, int Nc,
               const float* __restrict__ avs, const float* __restrict__ avd,
               float* __restrict__ as_out, float* __restrict__ ad_out) {
    extern __shared__ uint32_t sm[];

    const int tid  = threadIdx.x;
    const int warp = tid >> 5, lane = tid & 31;
    const int g    = lane >> 2, tig = lane & 3;
    const int l8   = lane & 7, sub = lane >> 3;
    const int wm   = (warp >> 1) * 32;   // 4 m-warps
    const int wn   = (warp & 1) * 32;    // 2 n-warps
    const int rowBlk = blockIdx.x * 128;
    const int colBlk = blockIdx.y * 64;
    const uint32_t* Wh32 = (const uint32_t*)Wh;
    const uint32_t* Wl32 = (const uint32_t*)Wl;
    const int Kp = K >> 1;
    const uint32_t sbase = (uint32_t)__cvta_generic_to_shared(sm);

    // ldmatrix per-thread row offsets (u32 units within array)
    const int rA0 = (wm + ((sub & 1) ? 8 : 0) + l8) * GS + ((sub >> 1) ? 4 : 0);
    const int rB0 = (wn + ((sub >> 1) ? 8 : 0) + l8) * GS + ((sub & 1) ? 4 : 0);

    // A global-load mapping: 4 float4 per thread
    const int ar  = tid >> 3;
    const int ac4 = (tid & 7) << 2;
    // B global-load mapping
    const int bn   = tid >> 2;
    const int bseg = tid & 3;
    const int bng  = colBlk + bn;
    const bool bok = (bng < Nc);

    float acc[2][4][4];
#pragma unroll
    for (int mi = 0; mi < 2; mi++)
#pragma unroll
        for (int ni = 0; ni < 4; ni++)
#pragma unroll
            for (int j = 0; j < 4; j++) acc[mi][ni][j] = 0.f;

    float4 pA[4];
    uint4 pBh, pBl;

    auto ldgA = [&](int k0) {
#pragma unroll
        for (int it = 0; it < 4; it++) {
            int r  = ar + it * 32;
            int gr = rowBlk + r;
            pA[it] = (gr < M) ? *(const float4*)&A[(size_t)gr * K + k0 + ac4]
                              : make_float4(0.f, 0.f, 0.f, 0.f);
        }
    };
    auto ldgB = [&](int k0) {
        pBh = make_uint4(0, 0, 0, 0);
        pBl = make_uint4(0, 0, 0, 0);
        if (bok) {
            pBh = *(const uint4*)(Wh32 + (size_t)bng * Kp + (k0 >> 1) + bseg * 4);
            pBl = *(const uint4*)(Wl32 + (size_t)bng * Kp + (k0 >> 1) + bseg * 4);
        }
    };
    auto stS = [&](int buf) {
        uint32_t* Ah = sm + buf * BUFU;
        uint32_t* Al = Ah + ASZ;
        uint32_t* Bh = Al + ASZ;
        uint32_t* Bl = Bh + BSZ;
#pragma unroll
        for (int it = 0; it < 4; it++) {
            int r = ar + it * 32;
            float4 v = pA[it];
            __nv_bfloat16 hx = __float2bfloat16(v.x);
            __nv_bfloat16 hy = __float2bfloat16(v.y);
            __nv_bfloat16 hz = __float2bfloat16(v.z);
            __nv_bfloat16 hw = __float2bfloat16(v.w);
            __nv_bfloat162 P0; P0.x = hx; P0.y = hy;
            __nv_bfloat162 P1; P1.x = hz; P1.y = hw;
            __nv_bfloat162 Q0 = __floats2bfloat162_rn(v.x - __bfloat162float(hx),
                                                      v.y - __bfloat162float(hy));
            __nv_bfloat162 Q1 = __floats2bfloat162_rn(v.z - __bfloat162float(hz),
                                                      v.w - __bfloat162float(hw));
            int base = r * GS + (ac4 >> 1);
            *(uint2*)&Ah[base] = make_uint2(*reinterpret_cast<uint32_t*>(&P0),
                                            *reinterpret_cast<uint32_t*>(&P1));
            *(uint2*)&Al[base] = make_uint2(*reinterpret_cast<uint32_t*>(&Q0),
                                            *reinterpret_cast<uint32_t*>(&Q1));
        }
        *(uint4*)&Bh[bn * GS + bseg * 4] = pBh;
        *(uint4*)&Bl[bn * GS + bseg * 4] = pBl;
    };
    auto compute = [&](int buf) {
        uint32_t aAh = sbase + (buf * BUFU) * 4;
        uint32_t aAl = aAh + ASZ * 4;
        uint32_t aBh = aAl + ASZ * 4;
        uint32_t aBl = aBh + BSZ * 4;
#pragma unroll
        for (int ks = 0; ks < 2; ks++) {
            const int kb = ks << 3;
            uint32_t ah[2][4], al[2][4], bh[4][2], bl[4][2];
#pragma unroll
            for (int mi = 0; mi < 2; mi++) {
                uint32_t off = (uint32_t)(rA0 + mi * 16 * GS + kb) * 4;
                ldsm4(ah[mi][0], ah[mi][1], ah[mi][2], ah[mi][3], aAh + off);
                ldsm4(al[mi][0], al[mi][1], al[mi][2], al[mi][3], aAl + off);
            }
#pragma unroll
            for (int nip = 0; nip < 2; nip++) {
                uint32_t off = (uint32_t)(rB0 + nip * 16 * GS + kb) * 4;
                ldsm4(bh[2 * nip][0], bh[2 * nip][1],
                      bh[2 * nip + 1][0], bh[2 * nip + 1][1], aBh + off);
                ldsm4(bl[2 * nip][0], bl[2 * nip][1],
                      bl[2 * nip + 1][0], bl[2 * nip + 1][1], aBl + off);
            }
#pragma unroll
            for (int mi = 0; mi < 2; mi++)
#pragma unroll
                for (int ni = 0; ni < 4; ni++) {
                    mma16816(acc[mi][ni], ah[mi][0], ah[mi][1], ah[mi][2], ah[mi][3],
                             bh[ni][0], bh[ni][1]);
                    mma16816(acc[mi][ni], ah[mi][0], ah[mi][1], ah[mi][2], ah[mi][3],
                             bl[ni][0], bl[ni][1]);
                    mma16816(acc[mi][ni], al[mi][0], al[mi][1], al[mi][2], al[mi][3],
                             bh[ni][0], bh[ni][1]);
                }
        }
    };

    const int nt = K / 32;
    ldgA(0); ldgB(0);
    stS(0);
    __syncthreads();
    ldgA(32); ldgB(32);

    for (int t = 0; t < nt; t++) {
        compute(t & 1);
        if (t + 1 < nt) {
            stS((t + 1) & 1);
            __syncthreads();
            if (t + 2 < nt) { ldgA((t + 2) * 32); ldgB((t + 2) * 32); }
        }
    }

    // ---- store C (fp32) ----
#pragma unroll
    for (int mi = 0; mi < 2; mi++) {
        int r0 = rowBlk + wm + mi * 16 + g;
        int r1 = r0 + 8;
#pragma unroll
        for (int ni = 0; ni < 4; ni++) {
            int c = colBlk + wn + ni * 8 + tig * 2;
            if (c >= Nc) continue;
            if (r0 < M)
                *(float2*)&C[(size_t)r0 * Nc + c] = make_float2(acc[mi][ni][0], acc[mi][ni][1]);
            if (r1 < M)
                *(float2*)&C[(size_t)r1 * Nc + c] = make_float2(acc[mi][ni][2], acc[mi][ni][3]);
        }
    }

    if constexpr (FUSE) {
        float vs[4][2], vd[4][2];
#pragma unroll
        for (int ni = 0; ni < 4; ni++) {
            int c = colBlk + wn + ni * 8 + tig * 2;
            vs[ni][0] = avs[c]; vs[ni][1] = avs[c + 1];
            vd[ni][0] = avd[c]; vd[ni][1] = avd[c + 1];
        }
#pragma unroll
        for (int mi = 0; mi < 2; mi++) {
#pragma unroll
            for (int half = 0; half < 2; half++) {
                int n0 = half * 2, n1 = n0 + 1;
                float psA = acc[mi][n0][0] * vs[n0][0] + acc[mi][n0][1] * vs[n0][1]
                          + acc[mi][n1][0] * vs[n1][0] + acc[mi][n1][1] * vs[n1][1];
                float pdA = acc[mi][n0][0] * vd[n0][0] + acc[mi][n0][1] * vd[n0][1]
                          + acc[mi][n1][0] * vd[n1][0] + acc[mi][n1][1] * vd[n1][1];
                float psB = acc[mi][n0][2] * vs[n0][0] + acc[mi][n0][3] * vs[n0][1]
                          + acc[mi][n1][2] * vs[n1][0] + acc[mi][n1][3] * vs[n1][1];
                float pdB = acc[mi][n0][2] * vd[n0][0] + acc[mi][n0][3] * vd[n0][1]
                          + acc[mi][n1][2] * vd[n1][0] + acc[mi][n1][3] * vd[n1][1];
#pragma unroll
                for (int off = 1; off <= 2; off <<= 1) {
                    psA += __shfl_xor_sync(0xffffffffu, psA, off);
                    pdA += __shfl_xor_sync(0xffffffffu, pdA, off);
                    psB += __shfl_xor_sync(0xffffffffu, psB, off);
                    pdB += __shfl_xor_sync(0xffffffffu, pdB, off);
                }
                if (tig == 0) {
                    int head = ((colBlk + wn) >> 4) + half;
                    int r0 = rowBlk + wm + mi * 16 + g;
                    int r1 = r0 + 8;
                    if (r0 < M) { as_out[r0 * NH + head] = psA; ad_out[r0 * NH + head] = pdA; }
                    if (r1 < M) { as_out[r1 * NH + head] = psB; ad_out[r1 * NH + head] = pdB; }
                }
            }
        }
    }
}

// ---------------- layer-2 alpha (H=1, C=40) ----------------
__global__ void k_alpha2(const float* __restrict__ gbuf,
                         const float* __restrict__ a_src, const float* __restrict__ a_dst,
                         float* __restrict__ as_arr, float* __restrict__ ad_arr) {
    int warp = (blockIdx.x * blockDim.x + threadIdx.x) >> 5;
    if (warp >= NN) return;
    int lane = threadIdx.x & 31;
    float v = gbuf[(size_t)warp * LBL + lane];
    float ps = v * a_src[lane];
    float pd = v * a_dst[lane];
    if (lane < 8) {
        float v2 = gbuf[(size_t)warp * LBL + lane + 32];
        ps += v2 * a_src[lane + 32];
        pd += v2 * a_dst[lane + 32];
    }
#pragma unroll
    for (int off = 16; off > 0; off >>= 1) {
        ps += __shfl_xor_sync(0xffffffffu, ps, off);
        pd += __shfl_xor_sync(0xffffffffu, pd, off);
    }
    if (lane == 0) { as_arr[warp] = ps; ad_arr[warp] = pd; }
}

// ---------------- aggregation: single pass, 4-way edge unroll ----------------
__global__ void k_aggregate(const float* __restrict__ gbuf,
                            const float* __restrict__ as_arr, const float* __restrict__ ad_arr,
                            const float* __restrict__ bias,
                            const float* __restrict__ gam, const float* __restrict__ bet,
                            const float* __restrict__ rm, const float* __restrict__ rv,
                            float* __restrict__ out) {
    int node = (blockIdx.x * blockDim.x + threadIdx.x) >> 5;
    if (node >= NN) return;
    int lane = threadIdx.x & 31;
    int h = lane >> 2;
    float adv = ad_arr[node * NH + h];
    int beg = g_offs[node];
    int cnt = g_counts[node];

    float ss[4] = {0.f, 0.f, 0.f, 0.f};
    float ax[4] = {0.f, 0.f, 0.f, 0.f};
    float ay[4] = {0.f, 0.f, 0.f, 0.f};
    float az[4] = {0.f, 0.f, 0.f, 0.f};
    float aw[4] = {0.f, 0.f, 0.f, 0.f};
    const float4* gb4 = (const float4*)gbuf;

    int e = 0;
    for (; e + 3 < cnt; e += 4) {
        int s[4];
#pragma unroll
        for (int j = 0; j < 4; j++) s[j] = g_esrc[beg + e + j];
        float av[4];
        float4 hvv[4];
#pragma unroll
        for (int j = 0; j < 4; j++) {
            av[j]  = as_arr[s[j] * NH + h];
            hvv[j] = gb4[(size_t)s[j] * (HC / 4) + lane];
        }
#pragma unroll
        for (int j = 0; j < 4; j++) {
            float ev = av[j] + adv;
            ev = ev > 0.f ? ev : NSLOPE * ev;
            float p = __expf(ev);
            ss[j] += p;
            ax[j] = fmaf(p, hvv[j].x, ax[j]);
            ay[j] = fmaf(p, hvv[j].y, ay[j]);
            az[j] = fmaf(p, hvv[j].z, az[j]);
            aw[j] = fmaf(p, hvv[j].w, aw[j]);
        }
    }
    for (; e < cnt; e++) {
        int s0 = g_esrc[beg + e];
        float a0 = as_arr[s0 * NH + h];
        float4 h0 = gb4[(size_t)s0 * (HC / 4) + lane];
        float ev = a0 + adv;
        ev = ev > 0.f ? ev : NSLOPE * ev;
        float p = __expf(ev);
        ss[0] += p;
        ax[0] = fmaf(p, h0.x, ax[0]); ay[0] = fmaf(p, h0.y, ay[0]);
        az[0] = fmaf(p, h0.z, az[0]); aw[0] = fmaf(p, h0.w, aw[0]);
    }
    float ssum = (ss[0] + ss[1]) + (ss[2] + ss[3]);
    float axs = (ax[0] + ax[1]) + (ax[2] + ax[3]);
    float ays = (ay[0] + ay[1]) + (ay[2] + ay[3]);
    float azs = (az[0] + az[1]) + (az[2] + az[3]);
    float aws = (aw[0] + aw[1]) + (aw[2] + aw[3]);

    float inv = 1.f / (ssum + 1e-16f);
    int ch = lane * 4;
    float vals[4] = { axs * inv, ays * inv, azs * inv, aws * inv };
    float4 o;
    float* op = &o.x;
#pragma unroll
    for (int j = 0; j < 4; j++) {
        float y = vals[j] + bias[ch + j];
        float sc = gam[ch + j] * rsqrtf(rv[ch + j] + BN_EPS);
        y = (y - rm[ch + j]) * sc + bet[ch + j];
        op[j] = y > 0.f ? y : ELU_A * expm1f(y);
    }
    *(float4*)&out[(size_t)node * HC + ch] = o;
}

__global__ void k_aggregate2(const float* __restrict__ gbuf,
                             const float* __restrict__ as_arr, const float* __restrict__ ad_arr,
                             const float* __restrict__ bias,
                             float* __restrict__ out) {
    int node = (blockIdx.x * blockDim.x + threadIdx.x) >> 5;
    if (node >= NN) return;
    int lane = threadIdx.x & 31;
    float adv = ad_arr[node];
    int beg = g_offs[node];
    int cnt = g_counts[node];

    float ssum0 = 0.f, ssum1 = 0.f;
    float a00 = 0.f, a10 = 0.f, a01 = 0.f, a11 = 0.f;
    int e = 0;
    for (; e + 1 < cnt; e += 2) {
        int s0 = g_esrc[beg + e];
        int s1 = g_esrc[beg + e + 1];
        float as0 = as_arr[s0];
        float as1 = as_arr[s1];
        float f00 = gbuf[(size_t)s0 * LBL + lane];
        float f01 = gbuf[(size_t)s1 * LBL + lane];
        float f10 = (lane < 8) ? gbuf[(size_t)s0 * LBL + lane + 32] : 0.f;
        float f11 = (lane < 8) ? gbuf[(size_t)s1 * LBL + lane + 32] : 0.f;
        float ev0 = as0 + adv; ev0 = ev0 > 0.f ? ev0 : NSLOPE * ev0;
        float ev1 = as1 + adv; ev1 = ev1 > 0.f ? ev1 : NSLOPE * ev1;
        float p0 = __expf(ev0), p1 = __expf(ev1);
        ssum0 += p0; ssum1 += p1;
        a00 = fmaf(p0, f00, a00); a10 = fmaf(p0, f10, a10);
        a01 = fmaf(p1, f01, a01); a11 = fmaf(p1, f11, a11);
    }
    if (e < cnt) {
        int s0 = g_esrc[beg + e];
        float as0 = as_arr[s0];
        float f00 = gbuf[(size_t)s0 * LBL + lane];
        float f10 = (lane < 8) ? gbuf[(size_t)s0 * LBL + lane + 32] : 0.f;
        float ev0 = as0 + adv; ev0 = ev0 > 0.f ? ev0 : NSLOPE * ev0;
        float p0 = __expf(ev0);
        ssum0 += p0;
        a00 = fmaf(p0, f00, a00); a10 = fmaf(p0, f10, a10);
    }
    float ssum = ssum0 + ssum1;
    float inv = 1.f / (ssum + 1e-16f);
    out[(size_t)node * LBL + lane] = (a00 + a01) * inv + bias[lane];
    if (lane < 8)
        out[(size_t)node * LBL + lane + 32] = (a10 + a11) * inv + bias[lane + 32];
}

// ---------------- launch ----------------
extern "C" void kernel_launch(void* const* d_in, const int* in_sizes, int n_in,
                              void* d_out, int out_size) {
    const float* x   = (const float*)d_in[0];
    const int*   ei  = (const int*)d_in[1];
    const float* W0  = (const float*)d_in[2];
    const float* as0 = (const float*)d_in[3];
    const float* ad0 = (const float*)d_in[4];
    const float* b0  = (const float*)d_in[5];
    const float* g0  = (const float*)d_in[6];
    const float* be0 = (const float*)d_in[7];
    const float* rm0 = (const float*)d_in[8];
    const float* rv0 = (const float*)d_in[9];
    const float* W1  = (const float*)d_in[10];
    const float* as1 = (const float*)d_in[11];
    const float* ad1 = (const float*)d_in[12];
    const float* b1  = (const float*)d_in[13];
    const float* g1  = (const float*)d_in[14];
    const float* be1 = (const float*)d_in[15];
    const float* rm1 = (const float*)d_in[16];
    const float* rv1 = (const float*)d_in[17];
    const float* W2  = (const float*)d_in[18];
    const float* as2 = (const float*)d_in[19];
    const float* ad2 = (const float*)d_in[20];
    const float* b2  = (const float*)d_in[21];
    float* out = (float*)d_out;

    float *gbuf, *hbuf, *asb, *adb, *as2b, *ad2b;
    __nv_bfloat16 *w0h, *w0l, *w1h, *w1l, *w2h, *w2l;
    cudaGetSymbolAddress((void**)&gbuf, g_gbuf);
    cudaGetSymbolAddress((void**)&hbuf, g_hbuf);
    cudaGetSymbolAddress((void**)&asb,  g_as);
    cudaGetSymbolAddress((void**)&adb,  g_ad);
    cudaGetSymbolAddress((void**)&as2b, g_as2);
    cudaGetSymbolAddress((void**)&ad2b, g_ad2);
    cudaGetSymbolAddress((void**)&w0h,  g_w0h);
    cudaGetSymbolAddress((void**)&w0l,  g_w0l);
    cudaGetSymbolAddress((void**)&w1h,  g_w1h);
    cudaGetSymbolAddress((void**)&w1l,  g_w1l);
    cudaGetSymbolAddress((void**)&w2h,  g_w2h);
    cudaGetSymbolAddress((void**)&w2l,  g_w2l);

    static bool attr_done = false;
    if (!attr_done) {
        cudaFuncSetAttribute(gemm_tc64<true>,
                             cudaFuncAttributeMaxDynamicSharedMemorySize, SMEMB);
        cudaFuncSetAttribute(gemm_tc64<false>,
                             cudaFuncAttributeMaxDynamicSharedMemorySize, SMEMB);
        attr_done = true;
    }

    const int TPB = 256;
    const int nodeBlocks = (NN + TPB - 1) / TPB;
    const int edgeBlocks = (ETOT + TPB - 1) / TPB;
    const int warpBlocks = (NN * 32 + TPB - 1) / TPB;
    const int mBlocks = (NN + 127) / 128;      // 391

    // weight split/transpose
    k_convW<<<(F_IN * HC + 255) / 256, 256>>>(W0, F_IN, HC, w0h, w0l);
    k_convW<<<(HC * HC + 255) / 256, 256>>>(W1, HC, HC, w1h, w1l);
    k_convW<<<(HC * LBL + 255) / 256, 256>>>(W2, HC, LBL, w2h, w2l);

    // GEMM0 + fused alpha0
    {
        dim3 grid(mBlocks, 2);
        gemm_tc64<true><<<grid, 256, SMEMB>>>(x, w0h, w0l, gbuf, NN, F_IN, HC,
                                              as0, ad0, asb, adb);
    }

    // CSR build
    k_zero<<<nodeBlocks, TPB>>>();
    k_count<<<edgeBlocks, TPB>>>(ei);
    k_assign<<<nodeBlocks, TPB>>>();
    k_fill<<<edgeBlocks, TPB>>>(ei);

    // layer 0 aggregate (+bias+BN+ELU)
    k_aggregate<<<warpBlocks, TPB>>>(gbuf, asb, adb, b0, g0, be0, rm0, rv0, hbuf);

    // layer 1
    {
        dim3 grid(mBlocks, 2);
        gemm_tc64<true><<<grid, 256, SMEMB>>>(hbuf, w1h, w1l, gbuf, NN, HC, HC,
                                              as1, ad1, asb, adb);
    }
    k_aggregate<<<warpBlocks, TPB>>>(gbuf, asb, adb, b1, g1, be1, rm1, rv1, hbuf);

    // layer 2 (Nc=40)
    {
        dim3 grid(mBlocks, 1);
        gemm_tc64<false><<<grid, 256, SMEMB>>>(hbuf, w2h, w2l, gbuf, NN, HC, LBL,
                                              nullptr, nullptr, nullptr, nullptr);
    }
    k_alpha2<<<warpBlocks, TPB>>>(gbuf, as2, ad2, as2b, ad2b);
    k_aggregate2<<<warpBlocks, TPB>>>(gbuf, as2b, ad2b, b2, out);
}

// round 16
// speedup vs baseline: 1.0761x; 1.0761x over previous
#include <cuda_runtime.h>
#include <cuda_bf16.h>
#include <math.h>
#include <stdint.h>

// ---------------- problem constants ----------------
#define NN      50000
#define EE      800000
#define ETOT    (EE + NN)
#define F_IN    512
#define NH      8
#define HC      128
#define LBL     40
#define BN_EPS  1e-5f
#define ELU_A   0.2f
#define NSLOPE  0.2f
#define GS      20      // smem row stride in u32 (80B) — conflict-free for LDSM

// ---------------- device scratch ----------------
__device__ float g_gbuf[(size_t)NN * HC];
__device__ float g_hbuf[(size_t)NN * HC];
__device__ float g_as[NN * NH];
__device__ float g_ad[NN * NH];
__device__ float g_as2[NN];
__device__ float g_ad2[NN];
__device__ int   g_counts[NN];
__device__ int   g_cursor[NN];
__device__ int   g_offs[NN];
__device__ int   g_esrc[ETOT];
__device__ int   g_total;
__device__ __nv_bfloat16 g_w0h[HC * F_IN];
__device__ __nv_bfloat16 g_w0l[HC * F_IN];
__device__ __nv_bfloat16 g_w1h[HC * HC];
__device__ __nv_bfloat16 g_w1l[HC * HC];
__device__ __nv_bfloat16 g_w2h[LBL * HC];
__device__ __nv_bfloat16 g_w2l[LBL * HC];

// ---------------- CSR build ----------------
__global__ void k_zero() {
    int i = blockIdx.x * blockDim.x + threadIdx.x;
    if (i < NN) { g_counts[i] = 0; g_cursor[i] = 0; }
    if (i == 0) g_total = 0;
}
__global__ void k_count(const int* __restrict__ ei) {
    int i = blockIdx.x * blockDim.x + threadIdx.x;
    if (i >= ETOT) return;
    int d = (i < EE) ? ei[EE + i] : (i - EE);
    atomicAdd(&g_counts[d], 1);
}
__global__ void k_assign() {
    int i = blockIdx.x * blockDim.x + threadIdx.x;
    if (i < NN) g_offs[i] = atomicAdd(&g_total, g_counts[i]);
}
__global__ void k_fill(const int* __restrict__ ei) {
    int i = blockIdx.x * blockDim.x + threadIdx.x;
    if (i >= ETOT) return;
    int s, d;
    if (i < EE) { s = ei[i]; d = ei[EE + i]; }
    else        { s = d = i - EE; }
    int slot = g_offs[d] + atomicAdd(&g_cursor[d], 1);
    g_esrc[slot] = s;
}

// ---------------- merged weight transpose + bf16 split (W0, W1, W2) --------
__global__ void k_convAll(const float* __restrict__ W0, const float* __restrict__ W1,
                          const float* __restrict__ W2,
                          __nv_bfloat16* __restrict__ w0h, __nv_bfloat16* __restrict__ w0l,
                          __nv_bfloat16* __restrict__ w1h, __nv_bfloat16* __restrict__ w1l,
                          __nv_bfloat16* __restrict__ w2h, __nv_bfloat16* __restrict__ w2l) {
    const int T0 = F_IN * HC;          // 65536
    const int T1 = HC * HC;            // 16384
    const int T2 = HC * LBL;           // 5120
    int i = blockIdx.x * blockDim.x + threadIdx.x;
    const float* W; __nv_bfloat16 *hi, *lo; int K, N, idx;
    if (i < T0)           { W = W0; hi = w0h; lo = w0l; K = F_IN; N = HC;  idx = i; }
    else if (i < T0 + T1) { W = W1; hi = w1h; lo = w1l; K = HC;   N = HC;  idx = i - T0; }
    else if (i < T0 + T1 + T2) { W = W2; hi = w2h; lo = w2l; K = HC; N = LBL; idx = i - T0 - T1; }
    else return;
    int k = idx / N, n = idx - k * N;
    float v = W[idx];
    __nv_bfloat16 h = __float2bfloat16(v);
    float r = v - __bfloat162float(h);
    hi[n * K + k] = h;
    lo[n * K + k] = __float2bfloat16(r);
}

// ---------------- asm helpers ----------------
__device__ __forceinline__ void mma16816(float* d,
                                         uint32_t a0, uint32_t a1, uint32_t a2, uint32_t a3,
                                         uint32_t b0, uint32_t b1) {
    asm volatile("mma.sync.aligned.m16n8k16.row.col.f32.bf16.bf16.f32 "
                 "{%0,%1,%2,%3}, {%4,%5,%6,%7}, {%8,%9}, {%0,%1,%2,%3};"
                 : "+f"(d[0]), "+f"(d[1]), "+f"(d[2]), "+f"(d[3])
                 : "r"(a0), "r"(a1), "r"(a2), "r"(a3), "r"(b0), "r"(b1));
}
__device__ __forceinline__ void ldsm4(uint32_t& r0, uint32_t& r1, uint32_t& r2, uint32_t& r3,
                                      uint32_t a) {
    asm volatile("ldmatrix.sync.aligned.m8n8.x4.shared.b16 {%0,%1,%2,%3}, [%4];"
                 : "=r"(r0), "=r"(r1), "=r"(r2), "=r"(r3) : "r"(a));
}

// ---------------- bf16x3 TC GEMM, 128x64 tile, 256 thr, 2 CTA/SM ------------
// R13 proven kernel: register double-buffering of global loads.
template<bool FUSE>
__global__ __launch_bounds__(256, 2)
void gemm_tc64(const float* __restrict__ A,
               const __nv_bfloat16* __restrict__ Wh,
               const __nv_bfloat16* __restrict__ Wl,
               float* __restrict__ C, int M, int K, int Nc,
               const float* __restrict__ avs, const float* __restrict__ avd,
               float* __restrict__ as_out, float* __restrict__ ad_out) {
    __shared__ uint32_t Ah[128 * GS];
    __shared__ uint32_t Al[128 * GS];
    __shared__ uint32_t Bh[64 * GS];
    __shared__ uint32_t Bl[64 * GS];

    const int tid  = threadIdx.x;
    const int warp = tid >> 5, lane = tid & 31;
    const int g    = lane >> 2, tig = lane & 3;
    const int l8   = lane & 7, sub = lane >> 3;
    const int wm   = (warp >> 1) * 32;   // 4 m-warps
    const int wn   = (warp & 1) * 32;    // 2 n-warps
    const int rowBlk = blockIdx.x * 128;
    const int colBlk = blockIdx.y * 64;
    const uint32_t* Wh32 = (const uint32_t*)Wh;
    const uint32_t* Wl32 = (const uint32_t*)Wl;
    const int Kp = K >> 1;

    const uint32_t sAh = (uint32_t)__cvta_generic_to_shared(Ah);
    const uint32_t sAl = (uint32_t)__cvta_generic_to_shared(Al);
    const uint32_t sBh = (uint32_t)__cvta_generic_to_shared(Bh);
    const uint32_t sBl = (uint32_t)__cvta_generic_to_shared(Bl);

    const int rA0 = (wm + ((sub & 1) ? 8 : 0) + l8) * GS + ((sub >> 1) ? 4 : 0);
    const int rB0 = (wn + ((sub >> 1) ? 8 : 0) + l8) * GS + ((sub & 1) ? 4 : 0);

    const int ar  = tid >> 3;
    const int ac4 = (tid & 7) << 2;
    const int bn   = tid >> 2;
    const int bseg = tid & 3;
    const int bng  = colBlk + bn;
    const bool bok = (bng < Nc);

    float acc[2][4][4];
#pragma unroll
    for (int mi = 0; mi < 2; mi++)
#pragma unroll
        for (int ni = 0; ni < 4; ni++)
#pragma unroll
            for (int j = 0; j < 4; j++) acc[mi][ni][j] = 0.f;

    float4 pA[4];
    uint4 pBh, pBl;

    auto ldgA = [&](int k0) {
#pragma unroll
        for (int it = 0; it < 4; it++) {
            int r  = ar + it * 32;
            int gr = rowBlk + r;
            pA[it] = (gr < M) ? *(const float4*)&A[(size_t)gr * K + k0 + ac4]
                              : make_float4(0.f, 0.f, 0.f, 0.f);
        }
    };
    auto ldgB = [&](int k0) {
        pBh = make_uint4(0, 0, 0, 0);
        pBl = make_uint4(0, 0, 0, 0);
        if (bok) {
            pBh = *(const uint4*)(Wh32 + (size_t)bng * Kp + (k0 >> 1) + bseg * 4);
            pBl = *(const uint4*)(Wl32 + (size_t)bng * Kp + (k0 >> 1) + bseg * 4);
        }
    };
    auto stS = [&]() {
#pragma unroll
        for (int it = 0; it < 4; it++) {
            int r = ar + it * 32;
            float4 v = pA[it];
            __nv_bfloat16 hx = __float2bfloat16(v.x);
            __nv_bfloat16 hy = __float2bfloat16(v.y);
            __nv_bfloat16 hz = __float2bfloat16(v.z);
            __nv_bfloat16 hw = __float2bfloat16(v.w);
            __nv_bfloat162 P0; P0.x = hx; P0.y = hy;
            __nv_bfloat162 P1; P1.x = hz; P1.y = hw;
            __nv_bfloat162 Q0 = __floats2bfloat162_rn(v.x - __bfloat162float(hx),
                                                      v.y - __bfloat162float(hy));
            __nv_bfloat162 Q1 = __floats2bfloat162_rn(v.z - __bfloat162float(hz),
                                                      v.w - __bfloat162float(hw));
            int base = r * GS + (ac4 >> 1);
            *(uint2*)&Ah[base] = make_uint2(*reinterpret_cast<uint32_t*>(&P0),
                                            *reinterpret_cast<uint32_t*>(&P1));
            *(uint2*)&Al[base] = make_uint2(*reinterpret_cast<uint32_t*>(&Q0),
                                            *reinterpret_cast<uint32_t*>(&Q1));
        }
        *(uint4*)&Bh[bn * GS + bseg * 4] = pBh;
        *(uint4*)&Bl[bn * GS + bseg * 4] = pBl;
    };

    const int nt = K / 32;
    ldgA(0); ldgB(0);

    for (int t = 0; t < nt; t++) {
        stS();
        __syncthreads();
        if (t + 1 < nt) { ldgA((t + 1) * 32); ldgB((t + 1) * 32); }

#pragma unroll
        for (int ks = 0; ks < 2; ks++) {
            const int kb = ks << 3;
            uint32_t ah[2][4], al[2][4], bh[4][2], bl[4][2];
#pragma unroll
            for (int mi = 0; mi < 2; mi++) {
                uint32_t off = (uint32_t)(rA0 + mi * 16 * GS + kb) * 4;
                ldsm4(ah[mi][0], ah[mi][1], ah[mi][2], ah[mi][3], sAh + off);
                ldsm4(al[mi][0], al[mi][1], al[mi][2], al[mi][3], sAl + off);
            }
#pragma unroll
            for (int nip = 0; nip < 2; nip++) {
                uint32_t off = (uint32_t)(rB0 + nip * 16 * GS + kb) * 4;
                ldsm4(bh[2 * nip][0], bh[2 * nip][1],
                      bh[2 * nip + 1][0], bh[2 * nip + 1][1], sBh + off);
                ldsm4(bl[2 * nip][0], bl[2 * nip][1],
                      bl[2 * nip + 1][0], bl[2 * nip + 1][1], sBl + off);
            }
#pragma unroll
            for (int mi = 0; mi < 2; mi++)
#pragma unroll
                for (int ni = 0; ni < 4; ni++) {
                    mma16816(acc[mi][ni], ah[mi][0], ah[mi][1], ah[mi][2], ah[mi][3],
                             bh[ni][0], bh[ni][1]);
                    mma16816(acc[mi][ni], ah[mi][0], ah[mi][1], ah[mi][2], ah[mi][3],
                             bl[ni][0], bl[ni][1]);
                    mma16816(acc[mi][ni], al[mi][0], al[mi][1], al[mi][2], al[mi][3],
                             bh[ni][0], bh[ni][1]);
                }
        }
        __syncthreads();
    }

    // ---- store C (fp32) ----
#pragma unroll
    for (int mi = 0; mi < 2; mi++) {
        int r0 = rowBlk + wm + mi * 16 + g;
        int r1 = r0 + 8;
#pragma unroll
        for (int ni = 0; ni < 4; ni++) {
            int c = colBlk + wn + ni * 8 + tig * 2;
            if (c >= Nc) continue;
            if (r0 < M)
                *(float2*)&C[(size_t)r0 * Nc + c] = make_float2(acc[mi][ni][0], acc[mi][ni][1]);
            if (r1 < M)
                *(float2*)&C[(size_t)r1 * Nc + c] = make_float2(acc[mi][ni][2], acc[mi][ni][3]);
        }
    }

    if constexpr (FUSE) {
        float vs[4][2], vd[4][2];
#pragma unroll
        for (int ni = 0; ni < 4; ni++) {
            int c = colBlk + wn + ni * 8 + tig * 2;
            vs[ni][0] = avs[c]; vs[ni][1] = avs[c + 1];
            vd[ni][0] = avd[c]; vd[ni][1] = avd[c + 1];
        }
#pragma unroll
        for (int mi = 0; mi < 2; mi++) {
#pragma unroll
            for (int half = 0; half < 2; half++) {
                int n0 = half * 2, n1 = n0 + 1;
                float psA = acc[mi][n0][0] * vs[n0][0] + acc[mi][n0][1] * vs[n0][1]
                          + acc[mi][n1][0] * vs[n1][0] + acc[mi][n1][1] * vs[n1][1];
                float pdA = acc[mi][n0][0] * vd[n0][0] + acc[mi][n0][1] * vd[n0][1]
                          + acc[mi][n1][0] * vd[n1][0] + acc[mi][n1][1] * vd[n1][1];
                float psB = acc[mi][n0][2] * vs[n0][0] + acc[mi][n0][3] * vs[n0][1]
                          + acc[mi][n1][2] * vs[n1][0] + acc[mi][n1][3] * vs[n1][1];
                float pdB = acc[mi][n0][2] * vd[n0][0] + acc[mi][n0][3] * vd[n0][1]
                          + acc[mi][n1][2] * vd[n1][0] + acc[mi][n1][3] * vd[n1][1];
#pragma unroll
                for (int off = 1; off <= 2; off <<= 1) {
                    psA += __shfl_xor_sync(0xffffffffu, psA, off);
                    pdA += __shfl_xor_sync(0xffffffffu, pdA, off);
                    psB += __shfl_xor_sync(0xffffffffu, psB, off);
                    pdB += __shfl_xor_sync(0xffffffffu, pdB, off);
                }
                if (tig == 0) {
                    int head = ((colBlk + wn) >> 4) + half;
                    int r0 = rowBlk + wm + mi * 16 + g;
                    int r1 = r0 + 8;
                    if (r0 < M) { as_out[r0 * NH + head] = psA; ad_out[r0 * NH + head] = pdA; }
                    if (r1 < M) { as_out[r1 * NH + head] = psB; ad_out[r1 * NH + head] = pdB; }
                }
            }
        }
    }
}

// ---------------- layer-2 alpha (H=1, C=40) ----------------
__global__ void k_alpha2(const float* __restrict__ gbuf,
                         const float* __restrict__ a_src, const float* __restrict__ a_dst,
                         float* __restrict__ as_arr, float* __restrict__ ad_arr) {
    int warp = (blockIdx.x * blockDim.x + threadIdx.x) >> 5;
    if (warp >= NN) return;
    int lane = threadIdx.x & 31;
    float v = gbuf[(size_t)warp * LBL + lane];
    float ps = v * a_src[lane];
    float pd = v * a_dst[lane];
    if (lane < 8) {
        float v2 = gbuf[(size_t)warp * LBL + lane + 32];
        ps += v2 * a_src[lane + 32];
        pd += v2 * a_dst[lane + 32];
    }
#pragma unroll
    for (int off = 16; off > 0; off >>= 1) {
        ps += __shfl_xor_sync(0xffffffffu, ps, off);
        pd += __shfl_xor_sync(0xffffffffu, pd, off);
    }
    if (lane == 0) { as_arr[warp] = ps; ad_arr[warp] = pd; }
}

// ---------------- aggregation: single pass, 2-way edge unroll ----------------
__global__ void k_aggregate(const float* __restrict__ gbuf,
                            const float* __restrict__ as_arr, const float* __restrict__ ad_arr,
                            const float* __restrict__ bias,
                            const float* __restrict__ gam, const float* __restrict__ bet,
                            const float* __restrict__ rm, const float* __restrict__ rv,
                            float* __restrict__ out) {
    int node = (blockIdx.x * blockDim.x + threadIdx.x) >> 5;
    if (node >= NN) return;
    int lane = threadIdx.x & 31;
    int h = lane >> 2;
    float adv = ad_arr[node * NH + h];
    int beg = g_offs[node];
    int cnt = g_counts[node];

    float ssum0 = 0.f, ssum1 = 0.f;
    float ax0 = 0.f, ay0 = 0.f, az0 = 0.f, aw0 = 0.f;
    float ax1 = 0.f, ay1 = 0.f, az1 = 0.f, aw1 = 0.f;
    const float4* gb4 = (const float4*)gbuf;

    int e = 0;
    for (; e + 1 < cnt; e += 2) {
        int s0 = g_esrc[beg + e];
        int s1 = g_esrc[beg + e + 1];
        float a0 = as_arr[s0 * NH + h];
        float a1 = as_arr[s1 * NH + h];
        float4 h0 = gb4[(size_t)s0 * (HC / 4) + lane];
        float4 h1 = gb4[(size_t)s1 * (HC / 4) + lane];
        float ev0 = a0 + adv; ev0 = ev0 > 0.f ? ev0 : NSLOPE * ev0;
        float ev1 = a1 + adv; ev1 = ev1 > 0.f ? ev1 : NSLOPE * ev1;
        float p0 = __expf(ev0), p1 = __expf(ev1);
        ssum0 += p0; ssum1 += p1;
        ax0 = fmaf(p0, h0.x, ax0); ay0 = fmaf(p0, h0.y, ay0);
        az0 = fmaf(p0, h0.z, az0); aw0 = fmaf(p0, h0.w, aw0);
        ax1 = fmaf(p1, h1.x, ax1); ay1 = fmaf(p1, h1.y, ay1);
        az1 = fmaf(p1, h1.z, az1); aw1 = fmaf(p1, h1.w, aw1);
    }
    if (e < cnt) {
        int s0 = g_esrc[beg + e];
        float a0 = as_arr[s0 * NH + h];
        float4 h0 = gb4[(size_t)s0 * (HC / 4) + lane];
        float ev0 = a0 + adv; ev0 = ev0 > 0.f ? ev0 : NSLOPE * ev0;
        float p0 = __expf(ev0);
        ssum0 += p0;
        ax0 = fmaf(p0, h0.x, ax0); ay0 = fmaf(p0, h0.y, ay0);
        az0 = fmaf(p0, h0.z, az0); aw0 = fmaf(p0, h0.w, aw0);
    }
    float ssum = ssum0 + ssum1;
    float ax = ax0 + ax1, ay = ay0 + ay1, az = az0 + az1, aw = aw0 + aw1;

    float inv = 1.f / (ssum + 1e-16f);
    int ch = lane * 4;
    float vals[4] = { ax * inv, ay * inv, az * inv, aw * inv };
    float4 o;
    float* op = &o.x;
#pragma unroll
    for (int j = 0; j < 4; j++) {
        float y = vals[j] + bias[ch + j];
        float sc = gam[ch + j] * rsqrtf(rv[ch + j] + BN_EPS);
        y = (y - rm[ch + j]) * sc + bet[ch + j];
        op[j] = y > 0.f ? y : ELU_A * expm1f(y);
    }
    *(float4*)&out[(size_t)node * HC + ch] = o;
}

__global__ void k_aggregate2(const float* __restrict__ gbuf,
                             const float* __restrict__ as_arr, const float* __restrict__ ad_arr,
                             const float* __restrict__ bias,
                             float* __restrict__ out) {
    int node = (blockIdx.x * blockDim.x + threadIdx.x) >> 5;
    if (node >= NN) return;
    int lane = threadIdx.x & 31;
    float adv = ad_arr[node];
    int beg = g_offs[node];
    int cnt = g_counts[node];

    float ssum0 = 0.f, ssum1 = 0.f;
    float a00 = 0.f, a10 = 0.f, a01 = 0.f, a11 = 0.f;
    int e = 0;
    for (; e + 1 < cnt; e += 2) {
        int s0 = g_esrc[beg + e];
        int s1 = g_esrc[beg + e + 1];
        float as0 = as_arr[s0];
        float as1 = as_arr[s1];
        float f00 = gbuf[(size_t)s0 * LBL + lane];
        float f01 = gbuf[(size_t)s1 * LBL + lane];
        float f10 = (lane < 8) ? gbuf[(size_t)s0 * LBL + lane + 32] : 0.f;
        float f11 = (lane < 8) ? gbuf[(size_t)s1 * LBL + lane + 32] : 0.f;
        float ev0 = as0 + adv; ev0 = ev0 > 0.f ? ev0 : NSLOPE * ev0;
        float ev1 = as1 + adv; ev1 = ev1 > 0.f ? ev1 : NSLOPE * ev1;
        float p0 = __expf(ev0), p1 = __expf(ev1);
        ssum0 += p0; ssum1 += p1;
        a00 = fmaf(p0, f00, a00); a10 = fmaf(p0, f10, a10);
        a01 = fmaf(p1, f01, a01); a11 = fmaf(p1, f11, a11);
    }
    if (e < cnt) {
        int s0 = g_esrc[beg + e];
        float as0 = as_arr[s0];
        float f00 = gbuf[(size_t)s0 * LBL + lane];
        float f10 = (lane < 8) ? gbuf[(size_t)s0 * LBL + lane + 32] : 0.f;
        float ev0 = as0 + adv; ev0 = ev0 > 0.f ? ev0 : NSLOPE * ev0;
        float p0 = __expf(ev0);
        ssum0 += p0;
        a00 = fmaf(p0, f00, a00); a10 = fmaf(p0, f10, a10);
    }
    float ssum = ssum0 + ssum1;
    float inv = 1.f / (ssum + 1e-16f);
    out[(size_t)node * LBL + lane] = (a00 + a01) * inv + bias[lane];
    if (lane < 8)
        out[(size_t)node * LBL + lane + 32] = (a10 + a11) * inv + bias[lane + 32];
}

// ---------------- launch ----------------
extern "C" void kernel_launch(void* const* d_in, const int* in_sizes, int n_in,
                              void* d_out, int out_size) {
    const float* x   = (const float*)d_in[0];
    const int*   ei  = (const int*)d_in[1];
    const float* W0  = (const float*)d_in[2];
    const float* as0 = (const float*)d_in[3];
    const float* ad0 = (const float*)d_in[4];
    const float* b0  = (const float*)d_in[5];
    const float* g0  = (const float*)d_in[6];
    const float* be0 = (const float*)d_in[7];
    const float* rm0 = (const float*)d_in[8];
    const float* rv0 = (const float*)d_in[9];
    const float* W1  = (const float*)d_in[10];
    const float* as1 = (const float*)d_in[11];
    const float* ad1 = (const float*)d_in[12];
    const float* b1  = (const float*)d_in[13];
    const float* g1  = (const float*)d_in[14];
    const float* be1 = (const float*)d_in[15];
    const float* rm1 = (const float*)d_in[16];
    const float* rv1 = (const float*)d_in[17];
    const float* W2  = (const float*)d_in[18];
    const float* as2 = (const float*)d_in[19];
    const float* ad2 = (const float*)d_in[20];
    const float* b2  = (const float*)d_in[21];
    float* out = (float*)d_out;

    float *gbuf, *hbuf, *asb, *adb, *as2b, *ad2b;
    __nv_bfloat16 *w0h, *w0l, *w1h, *w1l, *w2h, *w2l;
    cudaGetSymbolAddress((void**)&gbuf, g_gbuf);
    cudaGetSymbolAddress((void**)&hbuf, g_hbuf);
    cudaGetSymbolAddress((void**)&asb,  g_as);
    cudaGetSymbolAddress((void**)&adb,  g_ad);
    cudaGetSymbolAddress((void**)&as2b, g_as2);
    cudaGetSymbolAddress((void**)&ad2b, g_ad2);
    cudaGetSymbolAddress((void**)&w0h,  g_w0h);
    cudaGetSymbolAddress((void**)&w0l,  g_w0l);
    cudaGetSymbolAddress((void**)&w1h,  g_w1h);
    cudaGetSymbolAddress((void**)&w1l,  g_w1l);
    cudaGetSymbolAddress((void**)&w2h,  g_w2h);
    cudaGetSymbolAddress((void**)&w2l,  g_w2l);

    // one-time stream/event setup (first call is the uncaptured correctness run)
    static cudaStream_t s2 = nullptr;
    static cudaEvent_t evFork = nullptr, evJoin = nullptr;
    if (!s2) {
        cudaStreamCreate(&s2);
        cudaEventCreateWithFlags(&evFork, cudaEventDisableTiming);
        cudaEventCreateWithFlags(&evJoin, cudaEventDisableTiming);
    }

    const int TPB = 256;
    const int nodeBlocks = (NN + TPB - 1) / TPB;
    const int edgeBlocks = (ETOT + TPB - 1) / TPB;
    const int warpBlocks = (NN * 32 + TPB - 1) / TPB;
    const int mBlocks = (NN + 127) / 128;      // 391
    const int convTotal = F_IN * HC + HC * HC + HC * LBL;

    // ---- fork: CSR build on s2, concurrent with convW + GEMM0 on stream 0 --
    cudaEventRecord(evFork, 0);
    cudaStreamWaitEvent(s2, evFork, 0);
    k_zero<<<nodeBlocks, TPB, 0, s2>>>();
    k_count<<<edgeBlocks, TPB, 0, s2>>>(ei);
    k_assign<<<nodeBlocks, TPB, 0, s2>>>();
    k_fill<<<edgeBlocks, TPB, 0, s2>>>(ei);
    cudaEventRecord(evJoin, s2);

    // weight split/transpose (merged) + GEMM0 + fused alpha0 on stream 0
    k_convAll<<<(convTotal + 255) / 256, 256>>>(W0, W1, W2, w0h, w0l, w1h, w1l, w2h, w2l);
    {
        dim3 grid(mBlocks, 2);
        gemm_tc64<true><<<grid, 256>>>(x, w0h, w0l, gbuf, NN, F_IN, HC,
                                       as0, ad0, asb, adb);
    }

    // ---- join: aggregate needs CSR + GEMM0 ----
    cudaStreamWaitEvent(0, evJoin, 0);
    k_aggregate<<<warpBlocks, TPB>>>(gbuf, asb, adb, b0, g0, be0, rm0, rv0, hbuf);

    // layer 1
    {
        dim3 grid(mBlocks, 2);
        gemm_tc64<true><<<grid, 256>>>(hbuf, w1h, w1l, gbuf, NN, HC, HC,
                                       as1, ad1, asb, adb);
    }
    k_aggregate<<<warpBlocks, TPB>>>(gbuf, asb, adb, b1, g1, be1, rm1, rv1, hbuf);

    // layer 2 (Nc=40)
    {
        dim3 grid(mBlocks, 1);
        gemm_tc64<false><<<grid, 256>>>(hbuf, w2h, w2l, gbuf, NN, HC, LBL,
                                        nullptr, nullptr, nullptr, nullptr);
    }
    k_alpha2<<<warpBlocks, TPB>>>(gbuf, as2, ad2, as2b, ad2b);
    k_aggregate2<<<warpBlocks, TPB>>>(gbuf, as2b, ad2b, b2, out);
}

// round 17
// speedup vs baseline: 1.0788x; 1.0025x over previous
#include <cuda_runtime.h>
#include <cuda_bf16.h>
#include <math.h>
#include <stdint.h>

// ---------------- problem constants ----------------
#define NN      50000
#define EE      800000
#define ETOT    (EE + NN)
#define F_IN    512
#define NH      8
#define HC      128
#define LBL     40
#define BN_EPS  1e-5f
#define ELU_A   0.2f
#define NSLOPE  0.2f
#define GS      20      // smem row stride in u32 (80B) — conflict-free for LDSM

// ---------------- device scratch ----------------
__device__ float g_gbuf[(size_t)NN * HC];
__device__ float g_hbuf[(size_t)NN * HC];
__device__ float g_as[NN * NH];
__device__ float g_ad[NN * NH];
__device__ float g_as2[NN];
__device__ float g_ad2[NN];
__device__ int   g_counts[NN];
__device__ int   g_cursor[NN];
__device__ int   g_offs[NN];
__device__ int   g_esrc[ETOT];
__device__ int   g_total;
__device__ __nv_bfloat16 g_w0h[HC * F_IN];
__device__ __nv_bfloat16 g_w0l[HC * F_IN];
__device__ __nv_bfloat16 g_w1h[HC * HC];
__device__ __nv_bfloat16 g_w1l[HC * HC];
__device__ __nv_bfloat16 g_w2h[LBL * HC];
__device__ __nv_bfloat16 g_w2l[LBL * HC];

// ---------------- CSR build ----------------
__global__ void k_zero() {
    int i = blockIdx.x * blockDim.x + threadIdx.x;
    if (i < NN) { g_counts[i] = 0; g_cursor[i] = 0; }
    if (i == 0) g_total = 0;
}
__global__ void k_count(const int* __restrict__ ei) {
    int i = blockIdx.x * blockDim.x + threadIdx.x;
    if (i >= ETOT) return;
    int d = (i < EE) ? ei[EE + i] : (i - EE);
    atomicAdd(&g_counts[d], 1);
}
__global__ void k_assign() {
    int i = blockIdx.x * blockDim.x + threadIdx.x;
    if (i < NN) g_offs[i] = atomicAdd(&g_total, g_counts[i]);
}
__global__ void k_fill(const int* __restrict__ ei) {
    int i = blockIdx.x * blockDim.x + threadIdx.x;
    if (i >= ETOT) return;
    int s, d;
    if (i < EE) { s = ei[i]; d = ei[EE + i]; }
    else        { s = d = i - EE; }
    int slot = g_offs[d] + atomicAdd(&g_cursor[d], 1);
    g_esrc[slot] = s;
}

// ---------------- weight transpose + bf16 split ----------------
__global__ void k_convW(const float* __restrict__ W, int K, int N,
                        __nv_bfloat16* __restrict__ hi, __nv_bfloat16* __restrict__ lo) {
    int i = blockIdx.x * blockDim.x + threadIdx.x;
    if (i >= K * N) return;
    int k = i / N, n = i - k * N;
    float v = W[i];
    __nv_bfloat16 h = __float2bfloat16(v);
    float r = v - __bfloat162float(h);
    hi[n * K + k] = h;
    lo[n * K + k] = __float2bfloat16(r);
}

// ---------------- asm helpers ----------------
__device__ __forceinline__ void mma16816(float* d,
                                         uint32_t a0, uint32_t a1, uint32_t a2, uint32_t a3,
                                         uint32_t b0, uint32_t b1) {
    asm volatile("mma.sync.aligned.m16n8k16.row.col.f32.bf16.bf16.f32 "
                 "{%0,%1,%2,%3}, {%4,%5,%6,%7}, {%8,%9}, {%0,%1,%2,%3};"
                 : "+f"(d[0]), "+f"(d[1]), "+f"(d[2]), "+f"(d[3])
                 : "r"(a0), "r"(a1), "r"(a2), "r"(a3), "r"(b0), "r"(b1));
}
__device__ __forceinline__ void ldsm4(uint32_t& r0, uint32_t& r1, uint32_t& r2, uint32_t& r3,
                                      uint32_t a) {
    asm volatile("ldmatrix.sync.aligned.m8n8.x4.shared.b16 {%0,%1,%2,%3}, [%4];"
                 : "=r"(r0), "=r"(r1), "=r"(r2), "=r"(r3) : "r"(a));
}

// ---------------- bf16x3 TC GEMM, 128x64 tile, 256 thr, 2 CTA/SM ------------
// R13 kernel. Grid = (nColBlocks, mBlocks): column blocks of the same row band
// are adjacent in launch order, so the second reads A from L2 (halves A DRAM).
template<bool FUSE>
__global__ __launch_bounds__(256, 2)
void gemm_tc64(const float* __restrict__ A,
               const __nv_bfloat16* __restrict__ Wh,
               const __nv_bfloat16* __restrict__ Wl,
               float* __restrict__ C, int M, int K, int Nc,
               const float* __restrict__ avs, const float* __restrict__ avd,
               float* __restrict__ as_out, float* __restrict__ ad_out) {
    __shared__ uint32_t Ah[128 * GS];
    __shared__ uint32_t Al[128 * GS];
    __shared__ uint32_t Bh[64 * GS];
    __shared__ uint32_t Bl[64 * GS];

    const int tid  = threadIdx.x;
    const int warp = tid >> 5, lane = tid & 31;
    const int g    = lane >> 2, tig = lane & 3;
    const int l8   = lane & 7, sub = lane >> 3;
    const int wm   = (warp >> 1) * 32;   // 4 m-warps
    const int wn   = (warp & 1) * 32;    // 2 n-warps
    const int rowBlk = blockIdx.y * 128; // row band (slow axis)
    const int colBlk = blockIdx.x * 64;  // column block (fast axis)
    const uint32_t* Wh32 = (const uint32_t*)Wh;
    const uint32_t* Wl32 = (const uint32_t*)Wl;
    const int Kp = K >> 1;

    const uint32_t sAh = (uint32_t)__cvta_generic_to_shared(Ah);
    const uint32_t sAl = (uint32_t)__cvta_generic_to_shared(Al);
    const uint32_t sBh = (uint32_t)__cvta_generic_to_shared(Bh);
    const uint32_t sBl = (uint32_t)__cvta_generic_to_shared(Bl);

    const int rA0 = (wm + ((sub & 1) ? 8 : 0) + l8) * GS + ((sub >> 1) ? 4 : 0);
    const int rB0 = (wn + ((sub >> 1) ? 8 : 0) + l8) * GS + ((sub & 1) ? 4 : 0);

    const int ar  = tid >> 3;
    const int ac4 = (tid & 7) << 2;
    const int bn   = tid >> 2;
    const int bseg = tid & 3;
    const int bng  = colBlk + bn;
    const bool bok = (bng < Nc);

    float acc[2][4][4];
#pragma unroll
    for (int mi = 0; mi < 2; mi++)
#pragma unroll
        for (int ni = 0; ni < 4; ni++)
#pragma unroll
            for (int j = 0; j < 4; j++) acc[mi][ni][j] = 0.f;

    float4 pA[4];
    uint4 pBh, pBl;

    auto ldgA = [&](int k0) {
#pragma unroll
        for (int it = 0; it < 4; it++) {
            int r  = ar + it * 32;
            int gr = rowBlk + r;
            pA[it] = (gr < M) ? *(const float4*)&A[(size_t)gr * K + k0 + ac4]
                              : make_float4(0.f, 0.f, 0.f, 0.f);
        }
    };
    auto ldgB = [&](int k0) {
        pBh = make_uint4(0, 0, 0, 0);
        pBl = make_uint4(0, 0, 0, 0);
        if (bok) {
            pBh = *(const uint4*)(Wh32 + (size_t)bng * Kp + (k0 >> 1) + bseg * 4);
            pBl = *(const uint4*)(Wl32 + (size_t)bng * Kp + (k0 >> 1) + bseg * 4);
        }
    };
    auto stS = [&]() {
#pragma unroll
        for (int it = 0; it < 4; it++) {
            int r = ar + it * 32;
            float4 v = pA[it];
            __nv_bfloat16 hx = __float2bfloat16(v.x);
            __nv_bfloat16 hy = __float2bfloat16(v.y);
            __nv_bfloat16 hz = __float2bfloat16(v.z);
            __nv_bfloat16 hw = __float2bfloat16(v.w);
            __nv_bfloat162 P0; P0.x = hx; P0.y = hy;
            __nv_bfloat162 P1; P1.x = hz; P1.y = hw;
            __nv_bfloat162 Q0 = __floats2bfloat162_rn(v.x - __bfloat162float(hx),
                                                      v.y - __bfloat162float(hy));
            __nv_bfloat162 Q1 = __floats2bfloat162_rn(v.z - __bfloat162float(hz),
                                                      v.w - __bfloat162float(hw));
            int base = r * GS + (ac4 >> 1);
            *(uint2*)&Ah[base] = make_uint2(*reinterpret_cast<uint32_t*>(&P0),
                                            *reinterpret_cast<uint32_t*>(&P1));
            *(uint2*)&Al[base] = make_uint2(*reinterpret_cast<uint32_t*>(&Q0),
                                            *reinterpret_cast<uint32_t*>(&Q1));
        }
        *(uint4*)&Bh[bn * GS + bseg * 4] = pBh;
        *(uint4*)&Bl[bn * GS + bseg * 4] = pBl;
    };

    const int nt = K / 32;
    ldgA(0); ldgB(0);

    for (int t = 0; t < nt; t++) {
        stS();
        __syncthreads();
        if (t + 1 < nt) { ldgA((t + 1) * 32); ldgB((t + 1) * 32); }

#pragma unroll
        for (int ks = 0; ks < 2; ks++) {
            const int kb = ks << 3;
            uint32_t ah[2][4], al[2][4], bh[4][2], bl[4][2];
#pragma unroll
            for (int mi = 0; mi < 2; mi++) {
                uint32_t off = (uint32_t)(rA0 + mi * 16 * GS + kb) * 4;
                ldsm4(ah[mi][0], ah[mi][1], ah[mi][2], ah[mi][3], sAh + off);
                ldsm4(al[mi][0], al[mi][1], al[mi][2], al[mi][3], sAl + off);
            }
#pragma unroll
            for (int nip = 0; nip < 2; nip++) {
                uint32_t off = (uint32_t)(rB0 + nip * 16 * GS + kb) * 4;
                ldsm4(bh[2 * nip][0], bh[2 * nip][1],
                      bh[2 * nip + 1][0], bh[2 * nip + 1][1], sBh + off);
                ldsm4(bl[2 * nip][0], bl[2 * nip][1],
                      bl[2 * nip + 1][0], bl[2 * nip + 1][1], sBl + off);
            }
#pragma unroll
            for (int mi = 0; mi < 2; mi++)
#pragma unroll
                for (int ni = 0; ni < 4; ni++) {
                    mma16816(acc[mi][ni], ah[mi][0], ah[mi][1], ah[mi][2], ah[mi][3],
                             bh[ni][0], bh[ni][1]);
                    mma16816(acc[mi][ni], ah[mi][0], ah[mi][1], ah[mi][2], ah[mi][3],
                             bl[ni][0], bl[ni][1]);
                    mma16816(acc[mi][ni], al[mi][0], al[mi][1], al[mi][2], al[mi][3],
                             bh[ni][0], bh[ni][1]);
                }
        }
        __syncthreads();
    }

    // ---- store C (fp32) ----
#pragma unroll
    for (int mi = 0; mi < 2; mi++) {
        int r0 = rowBlk + wm + mi * 16 + g;
        int r1 = r0 + 8;
#pragma unroll
        for (int ni = 0; ni < 4; ni++) {
            int c = colBlk + wn + ni * 8 + tig * 2;
            if (c >= Nc) continue;
            if (r0 < M)
                *(float2*)&C[(size_t)r0 * Nc + c] = make_float2(acc[mi][ni][0], acc[mi][ni][1]);
            if (r1 < M)
                *(float2*)&C[(size_t)r1 * Nc + c] = make_float2(acc[mi][ni][2], acc[mi][ni][3]);
        }
    }

    if constexpr (FUSE) {
        float vs[4][2], vd[4][2];
#pragma unroll
        for (int ni = 0; ni < 4; ni++) {
            int c = colBlk + wn + ni * 8 + tig * 2;
            vs[ni][0] = avs[c]; vs[ni][1] = avs[c + 1];
            vd[ni][0] = avd[c]; vd[ni][1] = avd[c + 1];
        }
#pragma unroll
        for (int mi = 0; mi < 2; mi++) {
#pragma unroll
            for (int half = 0; half < 2; half++) {
                int n0 = half * 2, n1 = n0 + 1;
                float psA = acc[mi][n0][0] * vs[n0][0] + acc[mi][n0][1] * vs[n0][1]
                          + acc[mi][n1][0] * vs[n1][0] + acc[mi][n1][1] * vs[n1][1];
                float pdA = acc[mi][n0][0] * vd[n0][0] + acc[mi][n0][1] * vd[n0][1]
                          + acc[mi][n1][0] * vd[n1][0] + acc[mi][n1][1] * vd[n1][1];
                float psB = acc[mi][n0][2] * vs[n0][0] + acc[mi][n0][3] * vs[n0][1]
                          + acc[mi][n1][2] * vs[n1][0] + acc[mi][n1][3] * vs[n1][1];
                float pdB = acc[mi][n0][2] * vd[n0][0] + acc[mi][n0][3] * vd[n0][1]
                          + acc[mi][n1][2] * vd[n1][0] + acc[mi][n1][3] * vd[n1][1];
#pragma unroll
                for (int off = 1; off <= 2; off <<= 1) {
                    psA += __shfl_xor_sync(0xffffffffu, psA, off);
                    pdA += __shfl_xor_sync(0xffffffffu, pdA, off);
                    psB += __shfl_xor_sync(0xffffffffu, psB, off);
                    pdB += __shfl_xor_sync(0xffffffffu, pdB, off);
                }
                if (tig == 0) {
                    int head = ((colBlk + wn) >> 4) + half;
                    int r0 = rowBlk + wm + mi * 16 + g;
                    int r1 = r0 + 8;
                    if (r0 < M) { as_out[r0 * NH + head] = psA; ad_out[r0 * NH + head] = pdA; }
                    if (r1 < M) { as_out[r1 * NH + head] = psB; ad_out[r1 * NH + head] = pdB; }
                }
            }
        }
    }
}

// ---------------- layer-2 alpha (H=1, C=40) ----------------
__global__ void k_alpha2(const float* __restrict__ gbuf,
                         const float* __restrict__ a_src, const float* __restrict__ a_dst,
                         float* __restrict__ as_arr, float* __restrict__ ad_arr) {
    int warp = (blockIdx.x * blockDim.x + threadIdx.x) >> 5;
    if (warp >= NN) return;
    int lane = threadIdx.x & 31;
    float v = gbuf[(size_t)warp * LBL + lane];
    float ps = v * a_src[lane];
    float pd = v * a_dst[lane];
    if (lane < 8) {
        float v2 = gbuf[(size_t)warp * LBL + lane + 32];
        ps += v2 * a_src[lane + 32];
        pd += v2 * a_dst[lane + 32];
    }
#pragma unroll
    for (int off = 16; off > 0; off >>= 1) {
        ps += __shfl_xor_sync(0xffffffffu, ps, off);
        pd += __shfl_xor_sync(0xffffffffu, pd, off);
    }
    if (lane == 0) { as_arr[warp] = ps; ad_arr[warp] = pd; }
}

// ---------------- aggregation: single pass, 2-way edge unroll ----------------
__global__ void k_aggregate(const float* __restrict__ gbuf,
                            const float* __restrict__ as_arr, const float* __restrict__ ad_arr,
                            const float* __restrict__ bias,
                            const float* __restrict__ gam, const float* __restrict__ bet,
                            const float* __restrict__ rm, const float* __restrict__ rv,
                            float* __restrict__ out) {
    int node = (blockIdx.x * blockDim.x + threadIdx.x) >> 5;
    if (node >= NN) return;
    int lane = threadIdx.x & 31;
    int h = lane >> 2;
    float adv = ad_arr[node * NH + h];
    int beg = g_offs[node];
    int cnt = g_counts[node];

    float ssum0 = 0.f, ssum1 = 0.f;
    float ax0 = 0.f, ay0 = 0.f, az0 = 0.f, aw0 = 0.f;
    float ax1 = 0.f, ay1 = 0.f, az1 = 0.f, aw1 = 0.f;
    const float4* gb4 = (const float4*)gbuf;

    int e = 0;
    for (; e + 1 < cnt; e += 2) {
        int s0 = g_esrc[beg + e];
        int s1 = g_esrc[beg + e + 1];
        float a0 = as_arr[s0 * NH + h];
        float a1 = as_arr[s1 * NH + h];
        float4 h0 = gb4[(size_t)s0 * (HC / 4) + lane];
        float4 h1 = gb4[(size_t)s1 * (HC / 4) + lane];
        float ev0 = a0 + adv; ev0 = ev0 > 0.f ? ev0 : NSLOPE * ev0;
        float ev1 = a1 + adv; ev1 = ev1 > 0.f ? ev1 : NSLOPE * ev1;
        float p0 = __expf(ev0), p1 = __expf(ev1);
        ssum0 += p0; ssum1 += p1;
        ax0 = fmaf(p0, h0.x, ax0); ay0 = fmaf(p0, h0.y, ay0);
        az0 = fmaf(p0, h0.z, az0); aw0 = fmaf(p0, h0.w, aw0);
        ax1 = fmaf(p1, h1.x, ax1); ay1 = fmaf(p1, h1.y, ay1);
        az1 = fmaf(p1, h1.z, az1); aw1 = fmaf(p1, h1.w, aw1);
    }
    if (e < cnt) {
        int s0 = g_esrc[beg + e];
        float a0 = as_arr[s0 * NH + h];
        float4 h0 = gb4[(size_t)s0 * (HC / 4) + lane];
        float ev0 = a0 + adv; ev0 = ev0 > 0.f ? ev0 : NSLOPE * ev0;
        float p0 = __expf(ev0);
        ssum0 += p0;
        ax0 = fmaf(p0, h0.x, ax0); ay0 = fmaf(p0, h0.y, ay0);
        az0 = fmaf(p0, h0.z, az0); aw0 = fmaf(p0, h0.w, aw0);
    }
    float ssum = ssum0 + ssum1;
    float ax = ax0 + ax1, ay = ay0 + ay1, az = az0 + az1, aw = aw0 + aw1;

    float inv = 1.f / (ssum + 1e-16f);
    int ch = lane * 4;
    float vals[4] = { ax * inv, ay * inv, az * inv, aw * inv };
    float4 o;
    float* op = &o.x;
#pragma unroll
    for (int j = 0; j < 4; j++) {
        float y = vals[j] + bias[ch + j];
        float sc = gam[ch + j] * rsqrtf(rv[ch + j] + BN_EPS);
        y = (y - rm[ch + j]) * sc + bet[ch + j];
        op[j] = y > 0.f ? y : ELU_A * expm1f(y);
    }
    *(float4*)&out[(size_t)node * HC + ch] = o;
}

__global__ void k_aggregate2(const float* __restrict__ gbuf,
                             const float* __restrict__ as_arr, const float* __restrict__ ad_arr,
                             const float* __restrict__ bias,
                             float* __restrict__ out) {
    int node = (blockIdx.x * blockDim.x + threadIdx.x) >> 5;
    if (node >= NN) return;
    int lane = threadIdx.x & 31;
    float adv = ad_arr[node];
    int beg = g_offs[node];
    int cnt = g_counts[node];

    float ssum0 = 0.f, ssum1 = 0.f;
    float a00 = 0.f, a10 = 0.f, a01 = 0.f, a11 = 0.f;
    int e = 0;
    for (; e + 1 < cnt; e += 2) {
        int s0 = g_esrc[beg + e];
        int s1 = g_esrc[beg + e + 1];
        float as0 = as_arr[s0];
        float as1 = as_arr[s1];
        float f00 = gbuf[(size_t)s0 * LBL + lane];
        float f01 = gbuf[(size_t)s1 * LBL + lane];
        float f10 = (lane < 8) ? gbuf[(size_t)s0 * LBL + lane + 32] : 0.f;
        float f11 = (lane < 8) ? gbuf[(size_t)s1 * LBL + lane + 32] : 0.f;
        float ev0 = as0 + adv; ev0 = ev0 > 0.f ? ev0 : NSLOPE * ev0;
        float ev1 = as1 + adv; ev1 = ev1 > 0.f ? ev1 : NSLOPE * ev1;
        float p0 = __expf(ev0), p1 = __expf(ev1);
        ssum0 += p0; ssum1 += p1;
        a00 = fmaf(p0, f00, a00); a10 = fmaf(p0, f10, a10);
        a01 = fmaf(p1, f01, a01); a11 = fmaf(p1, f11, a11);
    }
    if (e < cnt) {
        int s0 = g_esrc[beg + e];
        float as0 = as_arr[s0];
        float f00 = gbuf[(size_t)s0 * LBL + lane];
        float f10 = (lane < 8) ? gbuf[(size_t)s0 * LBL + lane + 32] : 0.f;
        float ev0 = as0 + adv; ev0 = ev0 > 0.f ? ev0 : NSLOPE * ev0;
        float p0 = __expf(ev0);
        ssum0 += p0;
        a00 = fmaf(p0, f00, a00); a10 = fmaf(p0, f10, a10);
    }
    float ssum = ssum0 + ssum1;
    float inv = 1.f / (ssum + 1e-16f);
    out[(size_t)node * LBL + lane] = (a00 + a01) * inv + bias[lane];
    if (lane < 8)
        out[(size_t)node * LBL + lane + 32] = (a10 + a11) * inv + bias[lane + 32];
}

// ---------------- launch ----------------
extern "C" void kernel_launch(void* const* d_in, const int* in_sizes, int n_in,
                              void* d_out, int out_size) {
    const float* x   = (const float*)d_in[0];
    const int*   ei  = (const int*)d_in[1];
    const float* W0  = (const float*)d_in[2];
    const float* as0 = (const float*)d_in[3];
    const float* ad0 = (const float*)d_in[4];
    const float* b0  = (const float*)d_in[5];
    const float* g0  = (const float*)d_in[6];
    const float* be0 = (const float*)d_in[7];
    const float* rm0 = (const float*)d_in[8];
    const float* rv0 = (const float*)d_in[9];
    const float* W1  = (const float*)d_in[10];
    const float* as1 = (const float*)d_in[11];
    const float* ad1 = (const float*)d_in[12];
    const float* b1  = (const float*)d_in[13];
    const float* g1  = (const float*)d_in[14];
    const float* be1 = (const float*)d_in[15];
    const float* rm1 = (const float*)d_in[16];
    const float* rv1 = (const float*)d_in[17];
    const float* W2  = (const float*)d_in[18];
    const float* as2 = (const float*)d_in[19];
    const float* ad2 = (const float*)d_in[20];
    const float* b2  = (const float*)d_in[21];
    float* out = (float*)d_out;

    float *gbuf, *hbuf, *asb, *adb, *as2b, *ad2b;
    __nv_bfloat16 *w0h, *w0l, *w1h, *w1l, *w2h, *w2l;
    cudaGetSymbolAddress((void**)&gbuf, g_gbuf);
    cudaGetSymbolAddress((void**)&hbuf, g_hbuf);
    cudaGetSymbolAddress((void**)&asb,  g_as);
    cudaGetSymbolAddress((void**)&adb,  g_ad);
    cudaGetSymbolAddress((void**)&as2b, g_as2);
    cudaGetSymbolAddress((void**)&ad2b, g_ad2);
    cudaGetSymbolAddress((void**)&w0h,  g_w0h);
    cudaGetSymbolAddress((void**)&w0l,  g_w0l);
    cudaGetSymbolAddress((void**)&w1h,  g_w1h);
    cudaGetSymbolAddress((void**)&w1l,  g_w1l);
    cudaGetSymbolAddress((void**)&w2h,  g_w2h);
    cudaGetSymbolAddress((void**)&w2l,  g_w2l);

    // one-time stream/event setup (first call is the uncaptured correctness run)
    static cudaStream_t s2 = nullptr;
    static cudaEvent_t evFork = nullptr, evJoin = nullptr;
    if (!s2) {
        cudaStreamCreate(&s2);
        cudaEventCreateWithFlags(&evFork, cudaEventDisableTiming);
        cudaEventCreateWithFlags(&evJoin, cudaEventDisableTiming);
    }

    const int TPB = 256;
    const int nodeBlocks = (NN + TPB - 1) / TPB;
    const int edgeBlocks = (ETOT + TPB - 1) / TPB;
    const int warpBlocks = (NN * 32 + TPB - 1) / TPB;
    const int mBlocks = (NN + 127) / 128;      // 391

    // ---- fork: W1/W2 conversion + CSR build on s2, concurrent with main ----
    cudaEventRecord(evFork, 0);
    cudaStreamWaitEvent(s2, evFork, 0);
    k_convW<<<(HC * HC + 255) / 256, 256, 0, s2>>>(W1, HC, HC, w1h, w1l);
    k_convW<<<(HC * LBL + 255) / 256, 256, 0, s2>>>(W2, HC, LBL, w2h, w2l);
    k_zero<<<nodeBlocks, TPB, 0, s2>>>();
    k_count<<<edgeBlocks, TPB, 0, s2>>>(ei);
    k_assign<<<nodeBlocks, TPB, 0, s2>>>();
    k_fill<<<edgeBlocks, TPB, 0, s2>>>(ei);
    cudaEventRecord(evJoin, s2);

    // main stream: W0 conversion + GEMM0 + fused alpha0
    k_convW<<<(F_IN * HC + 255) / 256, 256>>>(W0, F_IN, HC, w0h, w0l);
    {
        dim3 grid(2, mBlocks);            // col fast, row slow -> A L2 reuse
        gemm_tc64<true><<<grid, 256>>>(x, w0h, w0l, gbuf, NN, F_IN, HC,
                                       as0, ad0, asb, adb);
    }

    // ---- join: aggregate needs CSR + GEMM0 ----
    cudaStreamWaitEvent(0, evJoin, 0);
    k_aggregate<<<warpBlocks, TPB>>>(gbuf, asb, adb, b0, g0, be0, rm0, rv0, hbuf);

    // layer 1
    {
        dim3 grid(2, mBlocks);
        gemm_tc64<true><<<grid, 256>>>(hbuf, w1h, w1l, gbuf, NN, HC, HC,
                                       as1, ad1, asb, adb);
    }
    k_aggregate<<<warpBlocks, TPB>>>(gbuf, asb, adb, b1, g1, be1, rm1, rv1, hbuf);

    // layer 2 (Nc=40)
    {
        dim3 grid(1, mBlocks);
        gemm_tc64<false><<<grid, 256>>>(hbuf, w2h, w2l, gbuf, NN, HC, LBL,
                                        nullptr, nullptr, nullptr, nullptr);
    }
    k_alpha2<<<warpBlocks, TPB>>>(gbuf, as2, ad2, as2b, ad2b);
    k_aggregate2<<<warpBlocks, TPB>>>(gbuf, as2b, ad2b, b2, out);
}